// round 4
// baseline (speedup 1.0000x reference)
#include <cuda_runtime.h>

// OWA pooling: 3x3 / stride 2 / pad(0,1,0,1) over (16,224,224,64) f32 NHWC.
// Per output element: descending-sort the 9 window values, dot with kernel[:,c].
// One thread = one output pixel x 4 channels (float4) -> 4 independent sort lanes.

namespace {

// Published optimal 9-element sorting network: 25 comparators, depth 7.
// (Canonical "best known" network from the sorting-network tables.)
__device__ __constant__ const int NET25_A[25] =
  {0,1,2,4, 0,2,3,5, 0,1,4,7, 1,3,5, 0,2,3,6, 2,4,6, 1,3,5};
__device__ __constant__ const int NET25_B[25] =
  {3,7,5,8, 7,4,8,6, 2,3,5,8, 4,6,7, 1,4,5,8, 3,5,7, 2,4,6};

constexpr int B_DIM = 16;
constexpr int H_IN = 224, W_IN = 224;
constexpr int H_OUT = 112, W_OUT = 112;
constexpr int C4 = 16;                               // 64 channels / 4
constexpr int TOTAL4 = B_DIM * H_OUT * W_OUT * C4;   // 3,211,264
constexpr int BLOCK = 256;

__device__ __forceinline__ void cas4(float4& A, float4& B) {
  float t;
  t = fminf(A.x, B.x); B.x = fmaxf(A.x, B.x); A.x = t;
  t = fminf(A.y, B.y); B.y = fmaxf(A.y, B.y); A.y = t;
  t = fminf(A.z, B.z); B.z = fmaxf(A.z, B.z); A.z = t;
  t = fminf(A.w, B.w); B.w = fmaxf(A.w, B.w); A.w = t;
}

// Fully-inlined ascending sort of 9 float4 lanes (25 compare-exchanges).
// Comparator list written out literally so indices are compile-time constants
// (no dependence on __constant__ arrays at runtime).
__device__ __forceinline__ void sort9(float4 (&v)[9]) {
  cas4(v[0],v[3]); cas4(v[1],v[7]); cas4(v[2],v[5]); cas4(v[4],v[8]);
  cas4(v[0],v[7]); cas4(v[2],v[4]); cas4(v[3],v[8]); cas4(v[5],v[6]);
  cas4(v[0],v[2]); cas4(v[1],v[3]); cas4(v[4],v[5]); cas4(v[7],v[8]);
  cas4(v[1],v[4]); cas4(v[3],v[6]); cas4(v[5],v[7]);
  cas4(v[0],v[1]); cas4(v[2],v[4]); cas4(v[3],v[5]); cas4(v[6],v[8]);
  cas4(v[2],v[3]); cas4(v[4],v[5]); cas4(v[6],v[7]);
  cas4(v[1],v[2]); cas4(v[3],v[4]); cas4(v[5],v[6]);
}

} // namespace

__global__ __launch_bounds__(BLOCK)
void owa_pool_kernel(const float4* __restrict__ in4,
                     const float4* __restrict__ wk4,
                     float4* __restrict__ out4) {
  int tid = blockIdx.x * BLOCK + threadIdx.x;
  if (tid >= TOTAL4) return;

  int c4  = tid & (C4 - 1);
  int pix = tid >> 4;
  int ow  = pix % W_OUT;
  int t   = pix / W_OUT;
  int oh  = t % H_OUT;
  int b   = t / H_OUT;

  int y0 = oh * 2;
  int x0 = ow * 2;

  float4 v[9];
#pragma unroll
  for (int ky = 0; ky < 3; ++ky) {
    int y = y0 + ky;
    bool yok = (y < H_IN);
    int rowbase = (b * H_IN + y) * W_IN;
#pragma unroll
    for (int kx = 0; kx < 3; ++kx) {
      int x = x0 + kx;
      float4 val = make_float4(0.f, 0.f, 0.f, 0.f);
      if (yok && x < W_IN) val = __ldg(&in4[(rowbase + x) * C4 + c4]);
      v[ky * 3 + kx] = val;
    }
  }

  // Ascending sort; weight k applies to the k-th LARGEST -> pair v[i] with w[8-i].
  sort9(v);

  float4 acc = make_float4(0.f, 0.f, 0.f, 0.f);
#pragma unroll
  for (int k = 0; k < 9; ++k) {
    float4 w = __ldg(&wk4[(8 - k) * C4 + c4]);
    acc.x = fmaf(v[k].x, w.x, acc.x);
    acc.y = fmaf(v[k].y, w.y, acc.y);
    acc.z = fmaf(v[k].z, w.z, acc.z);
    acc.w = fmaf(v[k].w, w.w, acc.w);
  }

  out4[tid] = acc;
}

extern "C" void kernel_launch(void* const* d_in, const int* in_sizes, int n_in,
                              void* d_out, int out_size) {
  const float4* in4 = (const float4*)d_in[0];   // (16,224,224,64) f32
  const float4* wk4 = (const float4*)d_in[1];   // (9,64) f32
  float4* out4 = (float4*)d_out;                // (16,112,112,64) f32

  (void)in_sizes; (void)n_in; (void)out_size;
  int grid = (TOTAL4 + BLOCK - 1) / BLOCK;
  owa_pool_kernel<<<grid, BLOCK>>>(in4, wk4, out4);
}

// round 5
// speedup vs baseline: 1.1071x; 1.1071x over previous
#include <cuda_runtime.h>

// OWA pooling: 3x3 / stride 2 / pad(0,1,0,1) over (16,224,224,64) f32 NHWC.
// Per output element: descending-sort the 9 window values, dot with kernel[:,c].
// One thread = one output pixel x 4 channels (float4) -> 4 independent sort lanes.
//
// R5: pipe rebalancing. Pure-FMNMX compare-exchange puts all sort work on the
// alu pipe (measured 64% busy vs fma 9%). Hybrid CAS (s=a+b; hi=max(a,b);
// lo=s-hi) moves 2/3 of each routed comparator's work to the fma pipe.
// 14 of 25 comparators routed hybrid -> both pipes ~24us of work.

namespace {

constexpr int B_DIM = 16;
constexpr int H_IN = 224, W_IN = 224;
constexpr int H_OUT = 112, W_OUT = 112;
constexpr int C4 = 16;                               // 64 channels / 4
constexpr int TOTAL4 = B_DIM * H_OUT * W_OUT * C4;   // 3,211,264
constexpr int BLOCK = 256;

// Pure alu-pipe CAS: 2 FMNMX per lane.
__device__ __forceinline__ void cas4(float4& A, float4& B) {
  float t;
  t = fminf(A.x, B.x); B.x = fmaxf(A.x, B.x); A.x = t;
  t = fminf(A.y, B.y); B.y = fmaxf(A.y, B.y); A.y = t;
  t = fminf(A.z, B.z); B.z = fmaxf(A.z, B.z); A.z = t;
  t = fminf(A.w, B.w); B.w = fmaxf(A.w, B.w); A.w = t;
}

// Hybrid CAS: hi = max(a,b) exact (FMNMX, alu pipe);
//             lo = (a+b) - hi  (2x FADD, fma pipe). lo off by <= 1 ulp of (a+b).
__device__ __forceinline__ void cas4h(float4& A, float4& B) {
  float s, hi;
  s = A.x + B.x; hi = fmaxf(A.x, B.x); B.x = hi; A.x = s - hi;
  s = A.y + B.y; hi = fmaxf(A.y, B.y); B.y = hi; A.y = s - hi;
  s = A.z + B.z; hi = fmaxf(A.z, B.z); B.z = hi; A.z = s - hi;
  s = A.w + B.w; hi = fmaxf(A.w, B.w); B.w = hi; A.w = s - hi;
}

// Published optimal 9-element sorting network: 25 comparators, depth 7.
// Stages 1-3 and 2 comparators of stage 4 (14 total) routed hybrid.
__device__ __forceinline__ void sort9(float4 (&v)[9]) {
  cas4h(v[0],v[3]); cas4h(v[1],v[7]); cas4h(v[2],v[5]); cas4h(v[4],v[8]);
  cas4h(v[0],v[7]); cas4h(v[2],v[4]); cas4h(v[3],v[8]); cas4h(v[5],v[6]);
  cas4h(v[0],v[2]); cas4h(v[1],v[3]); cas4h(v[4],v[5]); cas4h(v[7],v[8]);
  cas4h(v[1],v[4]); cas4h(v[3],v[6]); cas4 (v[5],v[7]);
  cas4 (v[0],v[1]); cas4 (v[2],v[4]); cas4 (v[3],v[5]); cas4 (v[6],v[8]);
  cas4 (v[2],v[3]); cas4 (v[4],v[5]); cas4 (v[6],v[7]);
  cas4 (v[1],v[2]); cas4 (v[3],v[4]); cas4 (v[5],v[6]);
}

} // namespace

__global__ __launch_bounds__(BLOCK, 4)
void owa_pool_kernel(const float4* __restrict__ in4,
                     const float4* __restrict__ wk4,
                     float4* __restrict__ out4) {
  int tid = blockIdx.x * BLOCK + threadIdx.x;
  if (tid >= TOTAL4) return;

  int c4  = tid & (C4 - 1);
  int pix = tid >> 4;
  int ow  = pix % W_OUT;
  int t   = pix / W_OUT;
  int oh  = t % H_OUT;
  int b   = t / H_OUT;

  int y0 = oh * 2;
  int x0 = ow * 2;

  float4 v[9];
#pragma unroll
  for (int ky = 0; ky < 3; ++ky) {
    int y = y0 + ky;
    bool yok = (y < H_IN);
    int rowbase = (b * H_IN + y) * W_IN;
#pragma unroll
    for (int kx = 0; kx < 3; ++kx) {
      int x = x0 + kx;
      float4 val = make_float4(0.f, 0.f, 0.f, 0.f);
      if (yok && x < W_IN) val = __ldg(&in4[(rowbase + x) * C4 + c4]);
      v[ky * 3 + kx] = val;
    }
  }

  // Ascending sort; weight k applies to the k-th LARGEST -> pair v[i] with w[8-i].
  sort9(v);

  float4 acc = make_float4(0.f, 0.f, 0.f, 0.f);
#pragma unroll
  for (int k = 0; k < 9; ++k) {
    float4 w = __ldg(&wk4[(8 - k) * C4 + c4]);
    acc.x = fmaf(v[k].x, w.x, acc.x);
    acc.y = fmaf(v[k].y, w.y, acc.y);
    acc.z = fmaf(v[k].z, w.z, acc.z);
    acc.w = fmaf(v[k].w, w.w, acc.w);
  }

  out4[tid] = acc;
}

extern "C" void kernel_launch(void* const* d_in, const int* in_sizes, int n_in,
                              void* d_out, int out_size) {
  const float4* in4 = (const float4*)d_in[0];   // (16,224,224,64) f32
  const float4* wk4 = (const float4*)d_in[1];   // (9,64) f32
  float4* out4 = (float4*)d_out;                // (16,112,112,64) f32

  (void)in_sizes; (void)n_in; (void)out_size;
  int grid = (TOTAL4 + BLOCK - 1) / BLOCK;
  owa_pool_kernel<<<grid, BLOCK>>>(in4, wk4, out4);
}